// round 14
// baseline (speedup 1.0000x reference)
#include <cuda_runtime.h>
#include <cuda_fp16.h>
#include <cstdint>

// ---------------- problem constants ----------------
#define TOKENS   8192
#define NDIM     4096
#define KDIM     4096
#define NGROUPS  32

// ---------------- GEMM tiling ----------------
#define BM 128
#define BN 128
#define BK 64
#define STAGES 3
#define KITERS (KDIM / BK)                  // 64
#define NTILES ((NDIM / BN) * (TOKENS / BM))   // 2048
#define NCTAS  296                          // 2 per SM, persistent, EXACT residency
#define A_STAGE_BYTES (BM * BK * 2)         // 16384
#define B_STAGE_BYTES (BN * BK * 2)         // 16384
#define STAGE_BYTES   (A_STAGE_BYTES + B_STAGE_BYTES)  // 32768
#define SMEM_TOTAL    (STAGES * STAGE_BYTES)           // 98304 -> 2 CTAs/SM

// ---------------- scratch (device globals; no allocation) ----------------
__device__ uint16_t g_xh[(size_t)TOKENS * KDIM];   // 64 MB fp16
__device__ uint16_t g_wh[(size_t)NDIM * KDIM];     // 32 MB fp16
__device__ unsigned int g_cnt[KITERS];             // per-slice CTA completion count

// ---------------- PTX helpers (baseline ISA only) ----------------
__device__ __forceinline__ uint32_t smem_to_u32(const void* p) {
    uint32_t a;
    asm("{ .reg .u64 t; cvta.to.shared.u64 t, %1; cvt.u32.u64 %0, t; }" : "=r"(a) : "l"(p));
    return a;
}

#define CP_ASYNC16(dst, src) \
    asm volatile("cp.async.cg.shared.global [%0], [%1], 16;" :: "r"(dst), "l"(src) : "memory")
#define CP_COMMIT() asm volatile("cp.async.commit_group;" ::: "memory")
#define CP_WAIT(n)  asm volatile("cp.async.wait_group %0;" :: "n"(n) : "memory")

#define LDSM4(r0, r1, r2, r3, addr) \
    asm volatile("ldmatrix.sync.aligned.m8n8.x4.shared.b16 {%0,%1,%2,%3}, [%4];" \
                 : "=r"(r0), "=r"(r1), "=r"(r2), "=r"(r3) : "r"(addr))

#define MMA16816(c, a, b0, b1) \
    asm volatile("mma.sync.aligned.m16n8k16.row.col.f32.f16.f16.f32 " \
                 "{%0,%1,%2,%3}, {%4,%5,%6,%7}, {%8,%9}, {%0,%1,%2,%3};" \
                 : "+f"((c)[0]), "+f"((c)[1]), "+f"((c)[2]), "+f"((c)[3]) \
                 : "r"((a)[0]), "r"((a)[1]), "r"((a)[2]), "r"((a)[3]), "r"(b0), "r"(b1))

// ---------------- counter reset (per launch; graph-replay safe) ----------
__global__ void reset_kernel() {
    if (threadIdx.x < KITERS) g_cnt[threadIdx.x] = 0u;
}

// ---------------- in-GEMM slice conversion -------------------------------
// Slice s = k-columns [s*64, s*64+64) — wholly inside quant group s>>1.
// Each CTA converts a strided 1/296 share of x (8192x16 float4-chunks) and
// w (4096x16 int4-chunks) for the slice.
__device__ __forceinline__ void convert_slice(
    int s, int gtid,
    const float* __restrict__ x, const int* __restrict__ q,
    const float* __restrict__ ws, const float* __restrict__ wz)
{
    int g = s >> 1;
    for (int idx = gtid; idx < TOKENS * 16; idx += NCTAS * 128) {
        int row = idx >> 4, c4 = idx & 15;
        size_t off = (size_t)row * KDIM + (s << 6) + (c4 << 2);
        float4 v = *reinterpret_cast<const float4*>(x + off);
        uint16_t h[4];
        h[0] = __half_as_ushort(__float2half_rn(v.x));
        h[1] = __half_as_ushort(__float2half_rn(v.y));
        h[2] = __half_as_ushort(__float2half_rn(v.z));
        h[3] = __half_as_ushort(__float2half_rn(v.w));
        *reinterpret_cast<uint2*>(g_xh + off) = *reinterpret_cast<uint2*>(h);
    }
    for (int idx = gtid; idx < NDIM * 16; idx += NCTAS * 128) {
        int row = idx >> 4, c4 = idx & 15;
        float sc = ws[row * NGROUPS + g];
        float zz = wz[row * NGROUPS + g];
        size_t off = (size_t)row * KDIM + (s << 6) + (c4 << 2);
        int4 qv = *reinterpret_cast<const int4*>(q + off);
        uint16_t h[4];
        h[0] = __half_as_ushort(__float2half_rn((float)qv.x * sc + zz));
        h[1] = __half_as_ushort(__float2half_rn((float)qv.y * sc + zz));
        h[2] = __half_as_ushort(__float2half_rn((float)qv.z * sc + zz));
        h[3] = __half_as_ushort(__float2half_rn((float)qv.w * sc + zz));
        *reinterpret_cast<uint2*>(g_wh + off) = *reinterpret_cast<uint2*>(h);
    }
}

#define CONVERT_AND_MARK(s) do {                                \
    convert_slice((s), gtid, x, q, ws, wz);                     \
    __threadfence();                                            \
    __syncthreads();                                            \
    if (tid == 0) atomicAdd(&g_cnt[(s)], 1u);                   \
} while (0)

#define WAIT_SLICE(s) do {                                      \
    volatile unsigned int* _c = (volatile unsigned int*)&g_cnt[(s)]; \
    while (*_c < (unsigned)NCTAS) {}                            \
    __threadfence();                                            \
} while (0)

// ---------------- persistent GEMM + fused streamed conversion ------------
// 296 CTAs (2/SM, exact residency). MMA schedule byte-identical to R8/R12.
// Conversion of slice pos+6 at iteration end (tile 0 only); prefetch of
// tile-0 slice pf gated on g_cnt[pf] (normally already full, 4-iter lead).
__global__ void __launch_bounds__(128, 2) gemm_kernel(
    const float* __restrict__ x, const int* __restrict__ q,
    const float* __restrict__ ws, const float* __restrict__ wz,
    const float* __restrict__ bias, float* __restrict__ out)
{
    extern __shared__ char smem[];
    uint32_t sbase = smem_to_u32(smem);
    int tid = threadIdx.x, lane = tid & 31, wid = tid >> 5;
    int wm = wid & 1, wn = wid >> 1;                  // 2 x 2 warp grid
    int bid = blockIdx.x;
    int gtid = bid * 128 + tid;
    int nMine = (NTILES - bid + NCTAS - 1) / NCTAS;
    int totStream = nMine * KITERS;

    // ---- loader thread constants ----
    int r0 = tid >> 3, c0 = tid & 7;
    uint32_t dstA0 = r0 * 128 + ((c0 ^ (r0 & 7)) << 4);
    int srcRowA = r0, srcCol = c0 * 8;

    // ---- ldmatrix per-thread row bases (layout verified R2-R13) ----
    int mBase = wm * 64 + (lane & 15);
    int aHi   = (lane >> 4) & 1;
    int nBase = wn * 64 + (lane & 7) + ((lane & 16) ? 8 : 0);
    int bHi   = (lane >> 3) & 1;

#define A_ADDR(sA, mi, kk) ((sA) + ((mBase + (mi) * 16) * 128) + \
    (((((kk) << 1) | aHi) ^ ((mBase + (mi) * 16) & 7)) << 4))
#define B_ADDR(sB, p, kk) ((sB) + ((nBase + (p) * 16) * 128) + \
    (((((kk) << 1) | bHi) ^ ((nBase + (p) * 16) & 7)) << 4))

#define ISSUE_PF(pf) do {                                                      \
    int pj = (pf) >> 6;                                                        \
    int pk = ((pf) & 63) * BK;                                                 \
    int pt = bid + NCTAS * pj;                                                 \
    int pm0 = (pt >> 5) * BM, pn0 = (pt & 31) * BN;                            \
    uint32_t sS = sbase + ((pf) % STAGES) * STAGE_BYTES;                       \
    const uint16_t* pA = g_xh + (size_t)(pm0 + srcRowA) * KDIM + srcCol + pk;  \
    const uint16_t* pB = g_wh + (size_t)(pn0 + srcRowA) * KDIM + srcCol + pk;  \
    _Pragma("unroll")                                                          \
    for (int i = 0; i < 8; i++) {                                              \
        CP_ASYNC16(sS + dstA0 + i * 2048, pA + (size_t)i * 16 * KDIM);         \
        CP_ASYNC16(sS + A_STAGE_BYTES + dstA0 + i * 2048, pB + (size_t)i * 16 * KDIM); \
    } } while (0)

    // ---- prologue: convert slices 0..5, publish, wait 0..1, prefetch ----
#pragma unroll 1
    for (int s = 0; s < 6; s++) CONVERT_AND_MARK(s);
    WAIT_SLICE(0);
    WAIT_SLICE(1);
    ISSUE_PF(0); CP_COMMIT();
    ISSUE_PF(1); CP_COMMIT();

    int pos = 0;
    for (int j = 0; j < nMine; j++) {
        int t = bid + NCTAS * j;
        int m0 = (t >> 5) * BM, n0 = (t & 31) * BN;

        float acc[4][8][4];
#pragma unroll
        for (int mi = 0; mi < 4; mi++)
#pragma unroll
            for (int ni = 0; ni < 8; ni++)
#pragma unroll
                for (int e = 0; e < 4; e++) acc[mi][ni][e] = 0.f;

        for (int it = 0; it < KITERS; it++, pos++) {
            CP_WAIT(STAGES - 2);
            __syncthreads();

            uint32_t sA = sbase + (pos % STAGES) * STAGE_BYTES;
            uint32_t sB = sA + A_STAGE_BYTES;
            int pf = pos + STAGES - 1;

            // first fragments immediately after barrier
            uint32_t b[2][4][4];
            uint32_t a[2][4];
#pragma unroll
            for (int p = 0; p < 4; p++)
                LDSM4(b[0][p][0], b[0][p][1], b[0][p][2], b[0][p][3], B_ADDR(sB, p, 0));
            LDSM4(a[0][0], a[0][1], a[0][2], a[0][3], A_ADDR(sA, 0, 0));

            // uniform prefetch burst (R8 schedule); tile-0 slices gated
            if (pf < totStream) {
                if (pf < KITERS) WAIT_SLICE(pf);
                ISSUE_PF(pf);
            }
            CP_COMMIT();

            // pipelined MMA: idx = kk*4 + mi, fragments double-buffered
#pragma unroll
            for (int kk = 0; kk < 4; kk++) {
                int cb = kk & 1;
                if (kk < 3) {
#pragma unroll
                    for (int p = 0; p < 4; p++)
                        LDSM4(b[cb ^ 1][p][0], b[cb ^ 1][p][1], b[cb ^ 1][p][2], b[cb ^ 1][p][3],
                              B_ADDR(sB, p, kk + 1));
                }
#pragma unroll
                for (int mi = 0; mi < 4; mi++) {
                    int idx = kk * 4 + mi;
                    int ca = idx & 1;
                    if (idx < 15) {
                        int nidx = idx + 1;
                        int nkk = nidx >> 2, nmi = nidx & 3;
                        LDSM4(a[ca ^ 1][0], a[ca ^ 1][1], a[ca ^ 1][2], a[ca ^ 1][3],
                              A_ADDR(sA, nmi, nkk));
                    }
#pragma unroll
                    for (int ni = 0; ni < 8; ni++) {
                        uint32_t b0 = b[cb][ni >> 1][(ni & 1) * 2 + 0];
                        uint32_t b1 = b[cb][ni >> 1][(ni & 1) * 2 + 1];
                        MMA16816(acc[mi][ni], a[ca], b0, b1);
                    }
                }
            }

            // streamed conversion of slice pos+6 (tile 0 only), after MMAs
            int cs = pos + 6;
            if (cs < KITERS) CONVERT_AND_MARK(cs);
        }

        // ---- epilogue for tile t (next tile's loads already in flight) ----
        int mB = m0 + wm * 64 + (lane >> 2);
        int nB = n0 + wn * 64 + (lane & 3) * 2;
        float bv[16];
#pragma unroll
        for (int ni = 0; ni < 8; ni++) {
            bv[ni * 2 + 0] = __ldg(bias + nB + ni * 8);
            bv[ni * 2 + 1] = __ldg(bias + nB + ni * 8 + 1);
        }
#pragma unroll
        for (int mi = 0; mi < 4; mi++) {
#pragma unroll
            for (int ni = 0; ni < 8; ni++) {
                int m = mB + mi * 16;
                int n = nB + ni * 8;
                float2 v0 = {acc[mi][ni][0] + bv[ni * 2], acc[mi][ni][1] + bv[ni * 2 + 1]};
                float2 v1 = {acc[mi][ni][2] + bv[ni * 2], acc[mi][ni][3] + bv[ni * 2 + 1]};
                *reinterpret_cast<float2*>(out + (size_t)m * NDIM + n) = v0;
                *reinterpret_cast<float2*>(out + (size_t)(m + 8) * NDIM + n) = v1;
            }
        }
    }
}

// ---------------- host ----------------
extern "C" void kernel_launch(void* const* d_in, const int* in_sizes, int n_in,
                              void* d_out, int out_size) {
    (void)in_sizes; (void)n_in; (void)out_size;
    const float* x    = (const float*)d_in[0];
    const int*   q    = (const int*)d_in[1];
    const float* s    = (const float*)d_in[2];
    const float* z    = (const float*)d_in[3];
    const float* bias = (const float*)d_in[4];
    float* out = (float*)d_out;

    reset_kernel<<<1, 64>>>();

    cudaFuncSetAttribute(gemm_kernel, cudaFuncAttributeMaxDynamicSharedMemorySize, SMEM_TOTAL);
    gemm_kernel<<<NCTAS, 128, SMEM_TOTAL>>>(x, q, s, z, bias, out);
}

// round 15
// speedup vs baseline: 1.4811x; 1.4811x over previous
#include <cuda_runtime.h>
#include <cuda_fp16.h>
#include <cstdint>

// ---------------- problem constants ----------------
#define TOKENS   8192
#define NDIM     4096
#define KDIM     4096
#define NGROUPS  32

// ---------------- GEMM tiling ----------------
#define BM 128
#define BN 128
#define BK 64
#define STAGES 3
#define KITERS (KDIM / BK)                  // 64
#define NTILES ((NDIM / BN) * (TOKENS / BM))   // 32 * 64 = 2048
#define NCTAS  296                          // 2 per SM, persistent
#define A_STAGE_BYTES (BM * BK * 2)         // 16384
#define B_STAGE_BYTES (BN * BK * 2)         // 16384
#define STAGE_BYTES   (A_STAGE_BYTES + B_STAGE_BYTES)  // 32768
#define SMEM_TOTAL    (STAGES * STAGE_BYTES)           // 98304 -> 2 CTAs/SM

// ---------------- scratch (device globals; no allocation) ----------------
__device__ uint16_t g_xh[(size_t)TOKENS * KDIM];   // 64 MB fp16
__device__ uint16_t g_wh[(size_t)NDIM * KDIM];     // 32 MB fp16

// ---------------- PTX helpers (baseline ISA only) ----------------
__device__ __forceinline__ uint32_t smem_to_u32(const void* p) {
    uint32_t a;
    asm("{ .reg .u64 t; cvta.to.shared.u64 t, %1; cvt.u32.u64 %0, t; }" : "=r"(a) : "l"(p));
    return a;
}

#define CP_ASYNC16(dst, src) \
    asm volatile("cp.async.cg.shared.global [%0], [%1], 16;" :: "r"(dst), "l"(src) : "memory")
#define CP_COMMIT() asm volatile("cp.async.commit_group;" ::: "memory")
#define CP_WAIT(n)  asm volatile("cp.async.wait_group %0;" :: "n"(n) : "memory")

#define LDSM4(r0, r1, r2, r3, addr) \
    asm volatile("ldmatrix.sync.aligned.m8n8.x4.shared.b16 {%0,%1,%2,%3}, [%4];" \
                 : "=r"(r0), "=r"(r1), "=r"(r2), "=r"(r3) : "r"(addr))

#define MMA16816(c, a, b0, b1) \
    asm volatile("mma.sync.aligned.m16n8k16.row.col.f32.f16.f16.f32 " \
                 "{%0,%1,%2,%3}, {%4,%5,%6,%7}, {%8,%9}, {%0,%1,%2,%3};" \
                 : "+f"((c)[0]), "+f"((c)[1]), "+f"((c)[2]), "+f"((c)[3]) \
                 : "r"((a)[0]), "r"((a)[1]), "r"((a)[2]), "r"((a)[3]), "r"(b0), "r"(b1))

// ---------------- fused prepass: x -> fp16, w dequant -> fp16 ------------
#define XBLKS ((int)(((size_t)TOKENS * KDIM) / (256 * 8)))   // 16384
#define WBLKS ((int)(((size_t)NDIM * KDIM) / (256 * 8)))     // 8192

__global__ void __launch_bounds__(256) conv_fused_kernel(
    const float* __restrict__ x, const int* __restrict__ q,
    const float* __restrict__ s, const float* __restrict__ z,
    uint16_t* __restrict__ xh, uint16_t* __restrict__ wh)
{
    int b = blockIdx.x;
    if (b < XBLKS) {
        size_t i = ((size_t)b * 256 + threadIdx.x) * 8;
        float4 v0 = *reinterpret_cast<const float4*>(x + i);
        float4 v1 = *reinterpret_cast<const float4*>(x + i + 4);
        float vv[8] = {v0.x, v0.y, v0.z, v0.w, v1.x, v1.y, v1.z, v1.w};
        uint16_t h[8];
#pragma unroll
        for (int j = 0; j < 8; j++) h[j] = __half_as_ushort(__float2half_rn(vv[j]));
        *reinterpret_cast<uint4*>(xh + i) = *reinterpret_cast<uint4*>(h);
    } else {
        size_t i = ((size_t)(b - XBLKS) * 256 + threadIdx.x) * 8;
        int n = (int)(i >> 12);
        int k = (int)(i & 4095);
        int g = k >> 7;
        float sc = s[n * NGROUPS + g];
        float zz = z[n * NGROUPS + g];
        int4 q0 = *reinterpret_cast<const int4*>(q + i);
        int4 q1 = *reinterpret_cast<const int4*>(q + i + 4);
        int qq[8] = {q0.x, q0.y, q0.z, q0.w, q1.x, q1.y, q1.z, q1.w};
        uint16_t h[8];
#pragma unroll
        for (int j = 0; j < 8; j++)
            h[j] = __half_as_ushort(__float2half_rn((float)qq[j] * sc + zz));
        *reinterpret_cast<uint4*>(wh + i) = *reinterpret_cast<uint4*>(h);
    }
}

// ---------------- persistent GEMM ----------------------------------------
// 296 CTAs (2/SM), each runs 6-7 tiles with a continuous cp.async stage ring
// across tile boundaries: the tail iterations of tile t prefetch tile t+1's
// first k-chunks, so the pipe never drains and the epilogue overlaps loads.
// 128 threads = 4 warps (2m x 2n), warp tile 64x64, fragments double-buffered.
// This schedule is the empirical optimum (R8): uniform 16-LDGSTS burst right
// after the head fragment LDSMs, committed immediately. Seven alternative
// schedules (interleaved, warp-staggered, post-kk0, incremental-index,
// fused-convert) all measured equal or worse.
__global__ void __launch_bounds__(128, 2) gemm_kernel(const float* __restrict__ bias,
                                                      float* __restrict__ out) {
    extern __shared__ char smem[];
    uint32_t sbase = smem_to_u32(smem);
    int tid = threadIdx.x, lane = tid & 31, wid = tid >> 5;
    int wm = wid & 1, wn = wid >> 1;                  // 2 x 2 warp grid
    int bid = blockIdx.x;
    int nMine = (NTILES - bid + NCTAS - 1) / NCTAS;
    int totStream = nMine * KITERS;

    // ---- loader thread constants ----
    int r0 = tid >> 3, c0 = tid & 7;
    uint32_t dstA0 = r0 * 128 + ((c0 ^ (r0 & 7)) << 4);
    int srcRowA = r0, srcCol = c0 * 8;

    // ---- ldmatrix per-thread row bases ----
    int mBase = wm * 64 + (lane & 15);
    int aHi   = (lane >> 4) & 1;
    int nBase = wn * 64 + (lane & 7) + ((lane & 16) ? 8 : 0);
    int bHi   = (lane >> 3) & 1;

#define A_ADDR(sA, mi, kk) ((sA) + ((mBase + (mi) * 16) * 128) + \
    (((((kk) << 1) | aHi) ^ ((mBase + (mi) * 16) & 7)) << 4))
#define B_ADDR(sB, p, kk) ((sB) + ((nBase + (p) * 16) * 128) + \
    (((((kk) << 1) | bHi) ^ ((nBase + (p) * 16) & 7)) << 4))

    // full prefetch burst for stream position pf (self-contained)
#define ISSUE_PF(pf) do {                                                      \
    int pj = (pf) >> 6;                                                        \
    int pk = ((pf) & 63) * BK;                                                 \
    int pt = bid + NCTAS * pj;                                                 \
    int pm0 = (pt >> 5) * BM, pn0 = (pt & 31) * BN;                            \
    uint32_t sS = sbase + ((pf) % STAGES) * STAGE_BYTES;                       \
    const uint16_t* pA = g_xh + (size_t)(pm0 + srcRowA) * KDIM + srcCol + pk;  \
    const uint16_t* pB = g_wh + (size_t)(pn0 + srcRowA) * KDIM + srcCol + pk;  \
    _Pragma("unroll")                                                          \
    for (int i = 0; i < 8; i++) {                                              \
        CP_ASYNC16(sS + dstA0 + i * 2048, pA + (size_t)i * 16 * KDIM);         \
        CP_ASYNC16(sS + A_STAGE_BYTES + dstA0 + i * 2048, pB + (size_t)i * 16 * KDIM); \
    } } while (0)

    // ---- prologue: fill stream positions 0, 1 ----
#pragma unroll
    for (int p = 0; p < STAGES - 1; p++) {
        ISSUE_PF(p);
        CP_COMMIT();
    }

    int pos = 0;
    for (int j = 0; j < nMine; j++) {
        int t = bid + NCTAS * j;
        int m0 = (t >> 5) * BM, n0 = (t & 31) * BN;

        float acc[4][8][4];
#pragma unroll
        for (int mi = 0; mi < 4; mi++)
#pragma unroll
            for (int ni = 0; ni < 8; ni++)
#pragma unroll
                for (int e = 0; e < 4; e++) acc[mi][ni][e] = 0.f;

        for (int it = 0; it < KITERS; it++, pos++) {
            CP_WAIT(STAGES - 2);
            __syncthreads();

            uint32_t sA = sbase + (pos % STAGES) * STAGE_BYTES;
            uint32_t sB = sA + A_STAGE_BYTES;
            int pf = pos + STAGES - 1;

            // first fragments immediately after barrier
            uint32_t b[2][4][4];
            uint32_t a[2][4];
#pragma unroll
            for (int p = 0; p < 4; p++)
                LDSM4(b[0][p][0], b[0][p][1], b[0][p][2], b[0][p][3], B_ADDR(sB, p, 0));
            LDSM4(a[0][0], a[0][1], a[0][2], a[0][3], A_ADDR(sA, 0, 0));

            // uniform prefetch burst, committed immediately
            if (pf < totStream) ISSUE_PF(pf);
            CP_COMMIT();

            // pipelined MMA: idx = kk*4 + mi, fragments double-buffered
#pragma unroll
            for (int kk = 0; kk < 4; kk++) {
                int cb = kk & 1;
                if (kk < 3) {
#pragma unroll
                    for (int p = 0; p < 4; p++)
                        LDSM4(b[cb ^ 1][p][0], b[cb ^ 1][p][1], b[cb ^ 1][p][2], b[cb ^ 1][p][3],
                              B_ADDR(sB, p, kk + 1));
                }
#pragma unroll
                for (int mi = 0; mi < 4; mi++) {
                    int idx = kk * 4 + mi;
                    int ca = idx & 1;
                    if (idx < 15) {
                        int nidx = idx + 1;
                        int nkk = nidx >> 2, nmi = nidx & 3;
                        LDSM4(a[ca ^ 1][0], a[ca ^ 1][1], a[ca ^ 1][2], a[ca ^ 1][3],
                              A_ADDR(sA, nmi, nkk));
                    }
#pragma unroll
                    for (int ni = 0; ni < 8; ni++) {
                        uint32_t b0 = b[cb][ni >> 1][(ni & 1) * 2 + 0];
                        uint32_t b1 = b[cb][ni >> 1][(ni & 1) * 2 + 1];
                        MMA16816(acc[mi][ni], a[ca], b0, b1);
                    }
                }
            }
        }

        // ---- epilogue for tile t (next tile's loads already in flight) ----
        int mB = m0 + wm * 64 + (lane >> 2);
        int nB = n0 + wn * 64 + (lane & 3) * 2;
        float bv[16];
#pragma unroll
        for (int ni = 0; ni < 8; ni++) {
            bv[ni * 2 + 0] = __ldg(bias + nB + ni * 8);
            bv[ni * 2 + 1] = __ldg(bias + nB + ni * 8 + 1);
        }
#pragma unroll
        for (int mi = 0; mi < 4; mi++) {
#pragma unroll
            for (int ni = 0; ni < 8; ni++) {
                int m = mB + mi * 16;
                int n = nB + ni * 8;
                float2 v0 = {acc[mi][ni][0] + bv[ni * 2], acc[mi][ni][1] + bv[ni * 2 + 1]};
                float2 v1 = {acc[mi][ni][2] + bv[ni * 2], acc[mi][ni][3] + bv[ni * 2 + 1]};
                *reinterpret_cast<float2*>(out + (size_t)m * NDIM + n) = v0;
                *reinterpret_cast<float2*>(out + (size_t)(m + 8) * NDIM + n) = v1;
            }
        }
    }
}

// ---------------- host ----------------
extern "C" void kernel_launch(void* const* d_in, const int* in_sizes, int n_in,
                              void* d_out, int out_size) {
    (void)in_sizes; (void)n_in; (void)out_size;
    const float* x    = (const float*)d_in[0];
    const int*   q    = (const int*)d_in[1];
    const float* s    = (const float*)d_in[2];
    const float* z    = (const float*)d_in[3];
    const float* bias = (const float*)d_in[4];
    float* out = (float*)d_out;

    void *p_xh, *p_wh;
    cudaGetSymbolAddress(&p_xh, g_xh);
    cudaGetSymbolAddress(&p_wh, g_wh);

    conv_fused_kernel<<<XBLKS + WBLKS, 256>>>(x, q, s, z,
                                              (uint16_t*)p_xh, (uint16_t*)p_wh);

    cudaFuncSetAttribute(gemm_kernel, cudaFuncAttributeMaxDynamicSharedMemorySize, SMEM_TOTAL);
    gemm_kernel<<<NCTAS, 128, SMEM_TOTAL>>>(bias, out);
}

// round 16
// speedup vs baseline: 1.5020x; 1.0141x over previous
#include <cuda_runtime.h>
#include <cuda_fp16.h>
#include <cstdint>

// ---------------- problem constants ----------------
#define TOKENS   8192
#define NDIM     4096
#define KDIM     4096
#define NGROUPS  32

// ---------------- GEMM tiling ----------------
#define BM 128
#define BN 128
#define BK 64
#define STAGES 3
#define KITERS (KDIM / BK)                  // 64
#define NTILES ((NDIM / BN) * (TOKENS / BM))   // 2048
#define NCTAS  296                          // 2 per SM, persistent
#define A_STAGE_BYTES (BM * BK * 2)         // 16384
#define B_STAGE_BYTES (BN * BK * 2)         // 16384
#define STAGE_BYTES   (A_STAGE_BYTES + B_STAGE_BYTES)  // 32768
#define SM_NEXT       (STAGES * STAGE_BYTES)           // mailbox offset
#define SMEM_TOTAL    (SM_NEXT + 16)                   // 98320 -> 2 CTAs/SM

// ---------------- scratch (device globals; no allocation) ----------------
__device__ uint16_t g_xh[(size_t)TOKENS * KDIM];   // 64 MB fp16
__device__ uint16_t g_wh[(size_t)NDIM * KDIM];     // 32 MB fp16
__device__ unsigned int g_tile;                    // dynamic tile counter

// ---------------- PTX helpers (baseline ISA only) ----------------
__device__ __forceinline__ uint32_t smem_to_u32(const void* p) {
    uint32_t a;
    asm("{ .reg .u64 t; cvta.to.shared.u64 t, %1; cvt.u32.u64 %0, t; }" : "=r"(a) : "l"(p));
    return a;
}

#define CP_ASYNC16(dst, src) \
    asm volatile("cp.async.cg.shared.global [%0], [%1], 16;" :: "r"(dst), "l"(src) : "memory")
#define CP_COMMIT() asm volatile("cp.async.commit_group;" ::: "memory")
#define CP_WAIT(n)  asm volatile("cp.async.wait_group %0;" :: "n"(n) : "memory")

#define LDSM4(r0, r1, r2, r3, addr) \
    asm volatile("ldmatrix.sync.aligned.m8n8.x4.shared.b16 {%0,%1,%2,%3}, [%4];" \
                 : "=r"(r0), "=r"(r1), "=r"(r2), "=r"(r3) : "r"(addr))

#define MMA16816(c, a, b0, b1) \
    asm volatile("mma.sync.aligned.m16n8k16.row.col.f32.f16.f16.f32 " \
                 "{%0,%1,%2,%3}, {%4,%5,%6,%7}, {%8,%9}, {%0,%1,%2,%3};" \
                 : "+f"((c)[0]), "+f"((c)[1]), "+f"((c)[2]), "+f"((c)[3]) \
                 : "r"((a)[0]), "r"((a)[1]), "r"((a)[2]), "r"((a)[3]), "r"(b0), "r"(b1))

// ---------------- fused prepass: x -> fp16, w dequant -> fp16 ------------
#define XBLKS ((int)(((size_t)TOKENS * KDIM) / (256 * 8)))   // 16384
#define WBLKS ((int)(((size_t)NDIM * KDIM) / (256 * 8)))     // 8192

__global__ void __launch_bounds__(256) conv_fused_kernel(
    const float* __restrict__ x, const int* __restrict__ q,
    const float* __restrict__ s, const float* __restrict__ z,
    uint16_t* __restrict__ xh, uint16_t* __restrict__ wh)
{
    int b = blockIdx.x;
    if (b == 0 && threadIdx.x == 0) g_tile = NCTAS;   // reset work queue (stream-ordered before GEMM)
    if (b < XBLKS) {
        size_t i = ((size_t)b * 256 + threadIdx.x) * 8;
        float4 v0 = *reinterpret_cast<const float4*>(x + i);
        float4 v1 = *reinterpret_cast<const float4*>(x + i + 4);
        float vv[8] = {v0.x, v0.y, v0.z, v0.w, v1.x, v1.y, v1.z, v1.w};
        uint16_t h[8];
#pragma unroll
        for (int j = 0; j < 8; j++) h[j] = __half_as_ushort(__float2half_rn(vv[j]));
        *reinterpret_cast<uint4*>(xh + i) = *reinterpret_cast<uint4*>(h);
    } else {
        size_t i = ((size_t)(b - XBLKS) * 256 + threadIdx.x) * 8;
        int n = (int)(i >> 12);
        int k = (int)(i & 4095);
        int g = k >> 7;
        float sc = s[n * NGROUPS + g];
        float zz = z[n * NGROUPS + g];
        int4 q0 = *reinterpret_cast<const int4*>(q + i);
        int4 q1 = *reinterpret_cast<const int4*>(q + i + 4);
        int qq[8] = {q0.x, q0.y, q0.z, q0.w, q1.x, q1.y, q1.z, q1.w};
        uint16_t h[8];
#pragma unroll
        for (int j = 0; j < 8; j++)
            h[j] = __half_as_ushort(__float2half_rn((float)qq[j] * sc + zz));
        *reinterpret_cast<uint4*>(wh + i) = *reinterpret_cast<uint4*>(h);
    }
}

// ---------------- persistent GEMM with dynamic tile stealing -------------
// 296 CTAs (2/SM). MMA region + prefetch schedule byte-identical to the
// empirical optimum (R8/R15). Tile assignment is dynamic: first tile = bid,
// then an atomicAdd work queue, grabbed at it==KITERS-3 into an smem mailbox
// (published by the existing iteration-top barrier before iterations 62/63
// prefetch across the tile boundary). Removes the static 7-vs-6-tile tail
// imbalance and absorbs per-SM speed variance.
__global__ void __launch_bounds__(128, 2) gemm_kernel(const float* __restrict__ bias,
                                                      float* __restrict__ out) {
    extern __shared__ char smem[];
    uint32_t sbase = smem_to_u32(smem);
    int* s_next = (int*)(smem + SM_NEXT);
    int tid = threadIdx.x, lane = tid & 31, wid = tid >> 5;
    int wm = wid & 1, wn = wid >> 1;                  // 2 x 2 warp grid
    int bid = blockIdx.x;

    // ---- loader thread constants ----
    int r0 = tid >> 3, c0 = tid & 7;
    uint32_t dstA0 = r0 * 128 + ((c0 ^ (r0 & 7)) << 4);
    int srcRowA = r0, srcCol = c0 * 8;

    // ---- ldmatrix per-thread row bases ----
    int mBase = wm * 64 + (lane & 15);
    int aHi   = (lane >> 4) & 1;
    int nBase = wn * 64 + (lane & 7) + ((lane & 16) ? 8 : 0);
    int bHi   = (lane >> 3) & 1;

#define A_ADDR(sA, mi, kk) ((sA) + ((mBase + (mi) * 16) * 128) + \
    (((((kk) << 1) | aHi) ^ ((mBase + (mi) * 16) & 7)) << 4))
#define B_ADDR(sB, p, kk) ((sB) + ((nBase + (p) * 16) * 128) + \
    (((((kk) << 1) | bHi) ^ ((nBase + (p) * 16) & 7)) << 4))

    // prefetch burst: explicit (tile, k-iter, stream-pos) version
#define ISSUE_PF_TK(pt, pk, pfpos) do {                                        \
    int pm0 = ((pt) >> 5) * BM, pn0 = ((pt) & 31) * BN;                        \
    uint32_t sS = sbase + ((pfpos) % STAGES) * STAGE_BYTES;                    \
    const uint16_t* pA = g_xh + (size_t)(pm0 + srcRowA) * KDIM + srcCol + (pk) * BK; \
    const uint16_t* pB = g_wh + (size_t)(pn0 + srcRowA) * KDIM + srcCol + (pk) * BK; \
    _Pragma("unroll")                                                          \
    for (int i = 0; i < 8; i++) {                                              \
        CP_ASYNC16(sS + dstA0 + i * 2048, pA + (size_t)i * 16 * KDIM);         \
        CP_ASYNC16(sS + A_STAGE_BYTES + dstA0 + i * 2048, pB + (size_t)i * 16 * KDIM); \
    } } while (0)

    // ---- prologue: fill stream positions 0, 1 of the first (static) tile ----
    int curT = bid;
    ISSUE_PF_TK(curT, 0, 0);
    CP_COMMIT();
    ISSUE_PF_TK(curT, 1, 1);
    CP_COMMIT();

    int pos = 0;
    for (;;) {
        int m0 = (curT >> 5) * BM, n0 = (curT & 31) * BN;

        float acc[4][8][4];
#pragma unroll
        for (int mi = 0; mi < 4; mi++)
#pragma unroll
            for (int ni = 0; ni < 8; ni++)
#pragma unroll
                for (int e = 0; e < 4; e++) acc[mi][ni][e] = 0.f;

        for (int it = 0; it < KITERS; it++, pos++) {
            CP_WAIT(STAGES - 2);
            __syncthreads();

            uint32_t sA = sbase + (pos % STAGES) * STAGE_BYTES;
            uint32_t sB = sA + A_STAGE_BYTES;
            int pf = pos + STAGES - 1;

            // first fragments immediately after barrier
            uint32_t b[2][4][4];
            uint32_t a[2][4];
#pragma unroll
            for (int p = 0; p < 4; p++)
                LDSM4(b[0][p][0], b[0][p][1], b[0][p][2], b[0][p][3], B_ADDR(sB, p, 0));
            LDSM4(a[0][0], a[0][1], a[0][2], a[0][3], A_ADDR(sA, 0, 0));

            // uniform prefetch burst, committed immediately (R8 schedule)
            int kpf = it + STAGES - 1;
            if (kpf < KITERS) {
                ISSUE_PF_TK(curT, kpf, pf);
            } else {
                int nt = *s_next;   // published by this iteration's barrier
                if (nt < NTILES) ISSUE_PF_TK(nt, kpf - KITERS, pf);
            }
            CP_COMMIT();

            // pipelined MMA: idx = kk*4 + mi, fragments double-buffered
#pragma unroll
            for (int kk = 0; kk < 4; kk++) {
                int cb = kk & 1;
                if (kk < 3) {
#pragma unroll
                    for (int p = 0; p < 4; p++)
                        LDSM4(b[cb ^ 1][p][0], b[cb ^ 1][p][1], b[cb ^ 1][p][2], b[cb ^ 1][p][3],
                              B_ADDR(sB, p, kk + 1));
                }
#pragma unroll
                for (int mi = 0; mi < 4; mi++) {
                    int idx = kk * 4 + mi;
                    int ca = idx & 1;
                    if (idx < 15) {
                        int nidx = idx + 1;
                        int nkk = nidx >> 2, nmi = nidx & 3;
                        LDSM4(a[ca ^ 1][0], a[ca ^ 1][1], a[ca ^ 1][2], a[ca ^ 1][3],
                              A_ADDR(sA, nmi, nkk));
                    }
#pragma unroll
                    for (int ni = 0; ni < 8; ni++) {
                        uint32_t b0 = b[cb][ni >> 1][(ni & 1) * 2 + 0];
                        uint32_t b1 = b[cb][ni >> 1][(ni & 1) * 2 + 1];
                        MMA16816(acc[mi][ni], a[ca], b0, b1);
                    }
                }
            }

            // grab next tile 3 iterations before the boundary (one predicated
            // atomic; published by the next iteration-top barrier)
            if (it == KITERS - 3 && tid == 0)
                *s_next = (int)atomicAdd(&g_tile, 1u);
        }

        // ---- epilogue for tile curT (next tile's loads already in flight) --
        int mB = m0 + wm * 64 + (lane >> 2);
        int nB = n0 + wn * 64 + (lane & 3) * 2;
        float bv[16];
#pragma unroll
        for (int ni = 0; ni < 8; ni++) {
            bv[ni * 2 + 0] = __ldg(bias + nB + ni * 8);
            bv[ni * 2 + 1] = __ldg(bias + nB + ni * 8 + 1);
        }
#pragma unroll
        for (int mi = 0; mi < 4; mi++) {
#pragma unroll
            for (int ni = 0; ni < 8; ni++) {
                int m = mB + mi * 16;
                int n = nB + ni * 8;
                float2 v0 = {acc[mi][ni][0] + bv[ni * 2], acc[mi][ni][1] + bv[ni * 2 + 1]};
                float2 v1 = {acc[mi][ni][2] + bv[ni * 2], acc[mi][ni][3] + bv[ni * 2 + 1]};
                *reinterpret_cast<float2*>(out + (size_t)m * NDIM + n) = v0;
                *reinterpret_cast<float2*>(out + (size_t)(m + 8) * NDIM + n) = v1;
            }
        }

        int nt = *s_next;           // written at it==61, ordered by it==62/63 barriers
        if (nt >= NTILES) break;
        curT = nt;
    }
}

// ---------------- host ----------------
extern "C" void kernel_launch(void* const* d_in, const int* in_sizes, int n_in,
                              void* d_out, int out_size) {
    (void)in_sizes; (void)n_in; (void)out_size;
    const float* x    = (const float*)d_in[0];
    const int*   q    = (const int*)d_in[1];
    const float* s    = (const float*)d_in[2];
    const float* z    = (const float*)d_in[3];
    const float* bias = (const float*)d_in[4];
    float* out = (float*)d_out;

    void *p_xh, *p_wh;
    cudaGetSymbolAddress(&p_xh, g_xh);
    cudaGetSymbolAddress(&p_wh, g_wh);

    conv_fused_kernel<<<XBLKS + WBLKS, 256>>>(x, q, s, z,
                                              (uint16_t*)p_xh, (uint16_t*)p_wh);

    cudaFuncSetAttribute(gemm_kernel, cudaFuncAttributeMaxDynamicSharedMemorySize, SMEM_TOTAL);
    gemm_kernel<<<NCTAS, 128, SMEM_TOTAL>>>(bias, out);
}

// round 17
// speedup vs baseline: 1.5061x; 1.0027x over previous
#include <cuda_runtime.h>
#include <cuda_fp16.h>
#include <cstdint>

// ---------------- problem constants ----------------
#define TOKENS   8192
#define NDIM     4096
#define KDIM     4096
#define NGROUPS  32

// ---------------- GEMM tiling ----------------
#define BM 128
#define BN 128
#define BK 64
#define STAGES 3
#define KITERS (KDIM / BK)                  // 64
#define NTILES ((NDIM / BN) * (TOKENS / BM))   // 2048
#define NCTAS  296                          // 2 per SM, persistent
#define A_STAGE_BYTES (BM * BK * 2)         // 16384
#define B_STAGE_BYTES (BN * BK * 2)         // 16384
#define STAGE_BYTES   (A_STAGE_BYTES + B_STAGE_BYTES)  // 32768
#define SM_NEXT       (STAGES * STAGE_BYTES)           // mailbox offset
#define SMEM_TOTAL    (SM_NEXT + 16)                   // 98320 -> 2 CTAs/SM

// ---------------- scratch (device globals; no allocation) ----------------
__device__ uint16_t g_xh[(size_t)TOKENS * KDIM];   // 64 MB fp16
__device__ uint16_t g_wh[(size_t)NDIM * KDIM];     // 32 MB fp16
__device__ unsigned int g_tile;                    // dynamic tile counter

// ---------------- PTX helpers (baseline ISA only) ----------------
__device__ __forceinline__ uint32_t smem_to_u32(const void* p) {
    uint32_t a;
    asm("{ .reg .u64 t; cvta.to.shared.u64 t, %1; cvt.u32.u64 %0, t; }" : "=r"(a) : "l"(p));
    return a;
}

#define CP_ASYNC16(dst, src) \
    asm volatile("cp.async.cg.shared.global [%0], [%1], 16;" :: "r"(dst), "l"(src) : "memory")
#define CP_COMMIT() asm volatile("cp.async.commit_group;" ::: "memory")
#define CP_WAIT(n)  asm volatile("cp.async.wait_group %0;" :: "n"(n) : "memory")

#define LDSM4(r0, r1, r2, r3, addr) \
    asm volatile("ldmatrix.sync.aligned.m8n8.x4.shared.b16 {%0,%1,%2,%3}, [%4];" \
                 : "=r"(r0), "=r"(r1), "=r"(r2), "=r"(r3) : "r"(addr))

#define MMA16816(c, a, b0, b1) \
    asm volatile("mma.sync.aligned.m16n8k16.row.col.f32.f16.f16.f32 " \
                 "{%0,%1,%2,%3}, {%4,%5,%6,%7}, {%8,%9}, {%0,%1,%2,%3};" \
                 : "+f"((c)[0]), "+f"((c)[1]), "+f"((c)[2]), "+f"((c)[3]) \
                 : "r"((a)[0]), "r"((a)[1]), "r"((a)[2]), "r"((a)[3]), "r"(b0), "r"(b1))

// ---------------- fused prepass: x -> fp16, w dequant -> fp16 ------------
#define XBLKS ((int)(((size_t)TOKENS * KDIM) / (256 * 8)))   // 16384
#define WBLKS ((int)(((size_t)NDIM * KDIM) / (256 * 8)))     // 8192

__global__ void __launch_bounds__(256) conv_fused_kernel(
    const float* __restrict__ x, const int* __restrict__ q,
    const float* __restrict__ s, const float* __restrict__ z,
    uint16_t* __restrict__ xh, uint16_t* __restrict__ wh)
{
    int b = blockIdx.x;
    if (b == 0 && threadIdx.x == 0) g_tile = NCTAS;   // reset work queue (stream-ordered before GEMM)
    if (b < XBLKS) {
        size_t i = ((size_t)b * 256 + threadIdx.x) * 8;
        float4 v0 = *reinterpret_cast<const float4*>(x + i);
        float4 v1 = *reinterpret_cast<const float4*>(x + i + 4);
        float vv[8] = {v0.x, v0.y, v0.z, v0.w, v1.x, v1.y, v1.z, v1.w};
        uint16_t h[8];
#pragma unroll
        for (int j = 0; j < 8; j++) h[j] = __half_as_ushort(__float2half_rn(vv[j]));
        *reinterpret_cast<uint4*>(xh + i) = *reinterpret_cast<uint4*>(h);
    } else {
        size_t i = ((size_t)(b - XBLKS) * 256 + threadIdx.x) * 8;
        int n = (int)(i >> 12);
        int k = (int)(i & 4095);
        int g = k >> 7;
        float sc = s[n * NGROUPS + g];
        float zz = z[n * NGROUPS + g];
        int4 q0 = *reinterpret_cast<const int4*>(q + i);
        int4 q1 = *reinterpret_cast<const int4*>(q + i + 4);
        int qq[8] = {q0.x, q0.y, q0.z, q0.w, q1.x, q1.y, q1.z, q1.w};
        uint16_t h[8];
#pragma unroll
        for (int j = 0; j < 8; j++)
            h[j] = __half_as_ushort(__float2half_rn((float)qq[j] * sc + zz));
        *reinterpret_cast<uint4*>(wh + i) = *reinterpret_cast<uint4*>(h);
    }
}

// ---------------- persistent GEMM with dynamic tile stealing -------------
// 296 CTAs (2/SM). MMA region + prefetch schedule byte-identical to the
// empirical optimum (R8/R15). Tile assignment is dynamic: first tile = bid,
// then an atomicAdd work queue, grabbed at it==KITERS-3 into an smem mailbox
// (published by the existing iteration-top barrier before iterations 62/63
// prefetch across the tile boundary). Removes the static 7-vs-6-tile tail
// imbalance and absorbs per-SM speed variance.
__global__ void __launch_bounds__(128, 2) gemm_kernel(const float* __restrict__ bias,
                                                      float* __restrict__ out) {
    extern __shared__ char smem[];
    uint32_t sbase = smem_to_u32(smem);
    int* s_next = (int*)(smem + SM_NEXT);
    int tid = threadIdx.x, lane = tid & 31, wid = tid >> 5;
    int wm = wid & 1, wn = wid >> 1;                  // 2 x 2 warp grid
    int bid = blockIdx.x;

    // ---- loader thread constants ----
    int r0 = tid >> 3, c0 = tid & 7;
    uint32_t dstA0 = r0 * 128 + ((c0 ^ (r0 & 7)) << 4);
    int srcRowA = r0, srcCol = c0 * 8;

    // ---- ldmatrix per-thread row bases ----
    int mBase = wm * 64 + (lane & 15);
    int aHi   = (lane >> 4) & 1;
    int nBase = wn * 64 + (lane & 7) + ((lane & 16) ? 8 : 0);
    int bHi   = (lane >> 3) & 1;

#define A_ADDR(sA, mi, kk) ((sA) + ((mBase + (mi) * 16) * 128) + \
    (((((kk) << 1) | aHi) ^ ((mBase + (mi) * 16) & 7)) << 4))
#define B_ADDR(sB, p, kk) ((sB) + ((nBase + (p) * 16) * 128) + \
    (((((kk) << 1) | bHi) ^ ((nBase + (p) * 16) & 7)) << 4))

    // prefetch burst: explicit (tile, k-iter, stream-pos) version
#define ISSUE_PF_TK(pt, pk, pfpos) do {                                        \
    int pm0 = ((pt) >> 5) * BM, pn0 = ((pt) & 31) * BN;                        \
    uint32_t sS = sbase + ((pfpos) % STAGES) * STAGE_BYTES;                    \
    const uint16_t* pA = g_xh + (size_t)(pm0 + srcRowA) * KDIM + srcCol + (pk) * BK; \
    const uint16_t* pB = g_wh + (size_t)(pn0 + srcRowA) * KDIM + srcCol + (pk) * BK; \
    _Pragma("unroll")                                                          \
    for (int i = 0; i < 8; i++) {                                              \
        CP_ASYNC16(sS + dstA0 + i * 2048, pA + (size_t)i * 16 * KDIM);         \
        CP_ASYNC16(sS + A_STAGE_BYTES + dstA0 + i * 2048, pB + (size_t)i * 16 * KDIM); \
    } } while (0)

    // ---- prologue: fill stream positions 0, 1 of the first (static) tile ----
    int curT = bid;
    ISSUE_PF_TK(curT, 0, 0);
    CP_COMMIT();
    ISSUE_PF_TK(curT, 1, 1);
    CP_COMMIT();

    int pos = 0;
    for (;;) {
        int m0 = (curT >> 5) * BM, n0 = (curT & 31) * BN;

        float acc[4][8][4];
#pragma unroll
        for (int mi = 0; mi < 4; mi++)
#pragma unroll
            for (int ni = 0; ni < 8; ni++)
#pragma unroll
                for (int e = 0; e < 4; e++) acc[mi][ni][e] = 0.f;

        for (int it = 0; it < KITERS; it++, pos++) {
            CP_WAIT(STAGES - 2);
            __syncthreads();

            uint32_t sA = sbase + (pos % STAGES) * STAGE_BYTES;
            uint32_t sB = sA + A_STAGE_BYTES;
            int pf = pos + STAGES - 1;

            // first fragments immediately after barrier
            uint32_t b[2][4][4];
            uint32_t a[2][4];
#pragma unroll
            for (int p = 0; p < 4; p++)
                LDSM4(b[0][p][0], b[0][p][1], b[0][p][2], b[0][p][3], B_ADDR(sB, p, 0));
            LDSM4(a[0][0], a[0][1], a[0][2], a[0][3], A_ADDR(sA, 0, 0));

            // uniform prefetch burst, committed immediately (R8 schedule)
            int kpf = it + STAGES - 1;
            if (kpf < KITERS) {
                ISSUE_PF_TK(curT, kpf, pf);
            } else {
                int nt = *s_next;   // published by this iteration's barrier
                if (nt < NTILES) ISSUE_PF_TK(nt, kpf - KITERS, pf);
            }
            CP_COMMIT();

            // pipelined MMA: idx = kk*4 + mi, fragments double-buffered
#pragma unroll
            for (int kk = 0; kk < 4; kk++) {
                int cb = kk & 1;
                if (kk < 3) {
#pragma unroll
                    for (int p = 0; p < 4; p++)
                        LDSM4(b[cb ^ 1][p][0], b[cb ^ 1][p][1], b[cb ^ 1][p][2], b[cb ^ 1][p][3],
                              B_ADDR(sB, p, kk + 1));
                }
#pragma unroll
                for (int mi = 0; mi < 4; mi++) {
                    int idx = kk * 4 + mi;
                    int ca = idx & 1;
                    if (idx < 15) {
                        int nidx = idx + 1;
                        int nkk = nidx >> 2, nmi = nidx & 3;
                        LDSM4(a[ca ^ 1][0], a[ca ^ 1][1], a[ca ^ 1][2], a[ca ^ 1][3],
                              A_ADDR(sA, nmi, nkk));
                    }
#pragma unroll
                    for (int ni = 0; ni < 8; ni++) {
                        uint32_t b0 = b[cb][ni >> 1][(ni & 1) * 2 + 0];
                        uint32_t b1 = b[cb][ni >> 1][(ni & 1) * 2 + 1];
                        MMA16816(acc[mi][ni], a[ca], b0, b1);
                    }
                }
            }

            // grab next tile 3 iterations before the boundary (one predicated
            // atomic; published by the next iteration-top barrier)
            if (it == KITERS - 3 && tid == 0)
                *s_next = (int)atomicAdd(&g_tile, 1u);
        }

        // ---- epilogue for tile curT (next tile's loads already in flight) --
        int mB = m0 + wm * 64 + (lane >> 2);
        int nB = n0 + wn * 64 + (lane & 3) * 2;
        float bv[16];
#pragma unroll
        for (int ni = 0; ni < 8; ni++) {
            bv[ni * 2 + 0] = __ldg(bias + nB + ni * 8);
            bv[ni * 2 + 1] = __ldg(bias + nB + ni * 8 + 1);
        }
#pragma unroll
        for (int mi = 0; mi < 4; mi++) {
#pragma unroll
            for (int ni = 0; ni < 8; ni++) {
                int m = mB + mi * 16;
                int n = nB + ni * 8;
                float2 v0 = {acc[mi][ni][0] + bv[ni * 2], acc[mi][ni][1] + bv[ni * 2 + 1]};
                float2 v1 = {acc[mi][ni][2] + bv[ni * 2], acc[mi][ni][3] + bv[ni * 2 + 1]};
                *reinterpret_cast<float2*>(out + (size_t)m * NDIM + n) = v0;
                *reinterpret_cast<float2*>(out + (size_t)(m + 8) * NDIM + n) = v1;
            }
        }

        int nt = *s_next;           // written at it==61, ordered by it==62/63 barriers
        if (nt >= NTILES) break;
        curT = nt;
    }
}

// ---------------- host ----------------
extern "C" void kernel_launch(void* const* d_in, const int* in_sizes, int n_in,
                              void* d_out, int out_size) {
    (void)in_sizes; (void)n_in; (void)out_size;
    const float* x    = (const float*)d_in[0];
    const int*   q    = (const int*)d_in[1];
    const float* s    = (const float*)d_in[2];
    const float* z    = (const float*)d_in[3];
    const float* bias = (const float*)d_in[4];
    float* out = (float*)d_out;

    void *p_xh, *p_wh;
    cudaGetSymbolAddress(&p_xh, g_xh);
    cudaGetSymbolAddress(&p_wh, g_wh);

    conv_fused_kernel<<<XBLKS + WBLKS, 256>>>(x, q, s, z,
                                              (uint16_t*)p_xh, (uint16_t*)p_wh);

    cudaFuncSetAttribute(gemm_kernel, cudaFuncAttributeMaxDynamicSharedMemorySize, SMEM_TOTAL);
    gemm_kernel<<<NCTAS, 128, SMEM_TOTAL>>>(bias, out);
}